// round 4
// baseline (speedup 1.0000x reference)
#include <cuda_runtime.h>

// Nearest-neighbor 2x upsample, NHWC fp32, GB300 (sm_103a).
// In : (8,128,128,256) fp32 = 128 MiB ; Out: (8,256,256,256) = 512 MiB.
// Persistent single-wave grid-stride kernel: 1024 blocks x 256 thr (~7 CTAs/SM,
// all resident for the whole run -> no wave-transition drains). Each loop
// iteration front-batches 4 independent streaming float4 loads (MLP=4),
// then does 16 fully line-coalesced streaming stores.
//
// Fixed shapes: B=8, H=W=128, C=256, f=2. C4=64 float4/pixel.
// n4 = 8*128*128*64 = 8,388,608 float4. stride = 1024*256 = 262,144.
// iterations = 8 outer x 4 unrolled = 32 chunks/thread.

#define STRIDE (1024 * 256)

__device__ __forceinline__ int out_base(int idx)
{
    // idx = ((b*128 + h)*128 + w)*64 + c4  ->  out f4 idx of (2h,2w)
    const int c4 = idx & 63;
    const int w  = (idx >> 6) & 127;
    const int h  = (idx >> 13) & 127;
    const int b  = idx >> 20;
    return (b << 22) + (h << 15) + (w << 7) + c4;
}

__device__ __forceinline__ void store4(float4* __restrict__ out, int o, float4 v)
{
    __stcs(out + o,                  v);   // (2h,   2w)
    __stcs(out + o + 64,             v);   // (2h,   2w+1)
    __stcs(out + o + (1 << 14),      v);   // (2h+1, 2w)
    __stcs(out + o + (1 << 14) + 64, v);   // (2h+1, 2w+1)
}

__global__ __launch_bounds__(256) void upsample2x_persist(
    const float4* __restrict__ in, float4* __restrict__ out)
{
    const int tid = blockIdx.x * 256 + threadIdx.x;   // 0 .. 262143

    #pragma unroll
    for (int outer = 0; outer < 8; outer++) {
        const int i0 = tid + (outer * 4 + 0) * STRIDE;
        const int i1 = tid + (outer * 4 + 1) * STRIDE;
        const int i2 = tid + (outer * 4 + 2) * STRIDE;
        const int i3 = tid + (outer * 4 + 3) * STRIDE;

        // Front-batched independent loads (MLP = 4)
        const float4 a = __ldcs(in + i0);
        const float4 b = __ldcs(in + i1);
        const float4 c = __ldcs(in + i2);
        const float4 d = __ldcs(in + i3);

        store4(out, out_base(i0), a);
        store4(out, out_base(i1), b);
        store4(out, out_base(i2), c);
        store4(out, out_base(i3), d);
    }
}

extern "C" void kernel_launch(void* const* d_in, const int* in_sizes, int n_in,
                              void* d_out, int out_size)
{
    const float4* in  = (const float4*)d_in[0];
    float4*       out = (float4*)d_out;

    upsample2x_persist<<<1024, 256>>>(in, out);
}

// round 5
// speedup vs baseline: 1.0836x; 1.0836x over previous
#include <cuda_runtime.h>

// Nearest-neighbor 2x upsample, NHWC fp32, GB300 (sm_103a).
// In : (8,128,128,256) fp32 = 128 MiB ; Out: (8,256,256,256) = 512 MiB.
// R1 structure (best so far): one float4 per thread, 1 LDG + 4 fully
// line-coalesced STG. This round: write-through stores (__stwt) so the write
// stream goes straight through L2 to DRAM instead of as deferred dirty-line
// writebacks that interleave with demand reads at the memory controller
// (mixed-direction turnaround is the suspected source of the ~21% DRAM idle).
// __ldcs on the read keeps the single-use input from occupying L2 ways.
//
// Fixed shapes: B=8, H=W=128, C=256, factor=2. C4 = 64 float4/pixel.
// Total float4 = 8*128*128*64 = 8,388,608.

__global__ __launch_bounds__(256) void upsample2x_wt(
    const float4* __restrict__ in, float4* __restrict__ out)
{
    const int idx = blockIdx.x * 256 + threadIdx.x;   // 0 .. 8388607
    // idx = ((b*128 + h)*128 + w)*64 + c4
    const int c4 = idx & 63;
    const int w  = (idx >> 6) & 127;
    const int h  = (idx >> 13) & 127;
    const int b  = idx >> 20;

    const float4 v = __ldcs(in + idx);

    // out float4 index of (2h,2w): b<<22 | h<<15 | w<<7 | c4
    const int o = (b << 22) + (h << 15) + (w << 7) + c4;

    __stwt(out + o,                  v);   // (2h,   2w)
    __stwt(out + o + 64,             v);   // (2h,   2w+1)
    __stwt(out + o + (1 << 14),      v);   // (2h+1, 2w)
    __stwt(out + o + (1 << 14) + 64, v);   // (2h+1, 2w+1)
}

extern "C" void kernel_launch(void* const* d_in, const int* in_sizes, int n_in,
                              void* d_out, int out_size)
{
    const float4* in  = (const float4*)d_in[0];
    float4*       out = (float4*)d_out;

    const int n4 = 8 * 128 * 128 * 64;   // 8,388,608 float4
    upsample2x_wt<<<n4 / 256, 256>>>(in, out);
}

// round 6
// speedup vs baseline: 1.0847x; 1.0009x over previous
#include <cuda_runtime.h>

// FINAL — Nearest-neighbor 2x upsample, NHWC fp32, GB300 (sm_103a).
// In : x (8, 128, 128, 256) fp32 = 128 MiB ; Out: (8, 256, 256, 256) = 512 MiB.
//
// Input-centric: each thread loads one float4 of the input and stores it to
// the 4 (2x2) replicated output positions. Input read exactly once ->
// 640 MiB total DRAM traffic, the information-theoretic floor.
//
// Measured at 6.28 TB/s (79% DRAM busy). R2-R5 established that wider
// accesses (256-bit), higher per-thread MLP, persistent single-wave grids,
// and streaming/write-through cache policies are all neutral or worse:
// the kernel sits at the HBM ceiling for a 1:4 read:write interleaved
// stream (bus-turnaround bound), so this simplest/fastest variant is final.
//
// Fixed shapes (from reference setup_inputs): B=8, H=W=128, C=256, factor=2.
// C4 = C/4 = 64 float4 per pixel. All power-of-two -> shift/mask indexing.

__global__ __launch_bounds__(256) void upsample2x_kernel(
    const float4* __restrict__ in, float4* __restrict__ out)
{
    const int idx = blockIdx.x * blockDim.x + threadIdx.x;   // 0 .. 8388607
    // Decompose input float4 index: ((b*128 + h)*128 + w)*64 + c4
    const int c4 = idx & 63;
    const int w  = (idx >> 6) & 127;
    const int h  = (idx >> 13) & 127;
    const int b  = idx >> 20;

    const float4 v = in[idx];

    // Output float4 index: ((b*256 + 2h+dh)*256 + 2w+dw)*64 + c4
    //  b stride : 256*256*64 = 1<<22
    //  2h stride: 2*256*64   = h<<15 (dh adds 1<<14)
    //  2w stride: 2*64       = w<<7  (dw adds 64)
    const int o = (b << 22) + (h << 15) + (w << 7) + c4;

    out[o]                  = v;   // (2h,   2w)
    out[o + 64]             = v;   // (2h,   2w+1)
    out[o + (1 << 14)]      = v;   // (2h+1, 2w)
    out[o + (1 << 14) + 64] = v;   // (2h+1, 2w+1)
}

extern "C" void kernel_launch(void* const* d_in, const int* in_sizes, int n_in,
                              void* d_out, int out_size)
{
    const float4* in  = (const float4*)d_in[0];
    float4*       out = (float4*)d_out;

    // 8*128*128*256 floats / 4 = 8,388,608 float4 elements
    const int n4 = 8 * 128 * 128 * 64;
    const int threads = 256;
    const int blocks  = n4 / threads;  // 32768

    upsample2x_kernel<<<blocks, threads>>>(in, out);
}

// round 7
// speedup vs baseline: 1.0918x; 1.0066x over previous
#include <cuda_runtime.h>

// Nearest-neighbor 2x upsample, NHWC fp32, GB300 (sm_103a).
// In : x (8, 128, 128, 256) fp32 = 128 MiB ; Out: (8, 256, 256, 256) = 512 MiB.
//
// Input-centric: each thread loads one float4 of the input and stores it to
// the 4 (2x2) replicated output positions. Input read exactly once ->
// 640 MiB DRAM traffic, the floor. Measured wall: ~6.25 TB/s (79% DRAM busy);
// R2-R6 established width/MLP/persistence/cache-policy are all non-binding.
//
// This round's only change vs the best kernel: 512-thread blocks (grid 16384)
// to halve CTA launch/retire events (achieved occ was 75-77% vs 100%
// theoretical purely from scheduling transients across ~28 waves).
//
// Fixed shapes: B=8, H=W=128, C=256, factor=2. C4 = 64 float4/pixel.

__global__ __launch_bounds__(512) void upsample2x_kernel(
    const float4* __restrict__ in, float4* __restrict__ out)
{
    const int idx = blockIdx.x * 512 + threadIdx.x;   // 0 .. 8388607
    // Decompose input float4 index: ((b*128 + h)*128 + w)*64 + c4
    const int c4 = idx & 63;
    const int w  = (idx >> 6) & 127;
    const int h  = (idx >> 13) & 127;
    const int b  = idx >> 20;

    const float4 v = in[idx];

    // Output float4 index: ((b*256 + 2h+dh)*256 + 2w+dw)*64 + c4
    //  b stride : 256*256*64 = 1<<22
    //  2h stride: 2*256*64   = h<<15 (dh adds 1<<14)
    //  2w stride: 2*64       = w<<7  (dw adds 64)
    const int o = (b << 22) + (h << 15) + (w << 7) + c4;

    out[o]                  = v;   // (2h,   2w)
    out[o + 64]             = v;   // (2h,   2w+1)
    out[o + (1 << 14)]      = v;   // (2h+1, 2w)
    out[o + (1 << 14) + 64] = v;   // (2h+1, 2w+1)
}

extern "C" void kernel_launch(void* const* d_in, const int* in_sizes, int n_in,
                              void* d_out, int out_size)
{
    const float4* in  = (const float4*)d_in[0];
    float4*       out = (float4*)d_out;

    const int n4 = 8 * 128 * 128 * 64;   // 8,388,608 float4 elements
    const int threads = 512;
    const int blocks  = n4 / threads;    // 16384

    upsample2x_kernel<<<blocks, threads>>>(in, out);
}

// round 8
// speedup vs baseline: 1.1012x; 1.0086x over previous
#include <cuda_runtime.h>

// FINAL — Nearest-neighbor 2x upsample, NHWC fp32, GB300 (sm_103a).
// In : x (8, 128, 128, 256) fp32 = 128 MiB ; Out: (8, 256, 256, 256) = 512 MiB.
//
// Input-centric: each thread loads one float4 of the input and stores it to
// the 4 (2x2) replicated output positions. Input read exactly once ->
// 640 MiB DRAM traffic, the information-theoretic floor for this op.
//
// Measured wall across 6 structural variants (R1-R7): 6.15-6.29 TB/s
// (78-79% DRAM busy). Access width (128/256-bit), per-thread MLP (1/2/4),
// persistent single-wave grids, block size (256/512), and L2 cache policy
// (.cs/.wt) are all non-binding -- the limit is HBM controller read/write
// bus-turnaround for the inherent 1:4 read:write interleaved mix, which is
// not addressable from the SM side. This configuration had the best
// profiled duration (97.34 us) and is locked as final.
//
// Fixed shapes (reference setup_inputs): B=8, H=W=128, C=256, factor=2.
// C4 = C/4 = 64 float4 per pixel. All power-of-two -> shift/mask indexing.

__global__ __launch_bounds__(512) void upsample2x_kernel(
    const float4* __restrict__ in, float4* __restrict__ out)
{
    const int idx = blockIdx.x * 512 + threadIdx.x;   // 0 .. 8388607
    // Decompose input float4 index: ((b*128 + h)*128 + w)*64 + c4
    const int c4 = idx & 63;
    const int w  = (idx >> 6) & 127;
    const int h  = (idx >> 13) & 127;
    const int b  = idx >> 20;

    const float4 v = in[idx];

    // Output float4 index: ((b*256 + 2h+dh)*256 + 2w+dw)*64 + c4
    //  b stride : 256*256*64 = 1<<22
    //  2h stride: 2*256*64   = h<<15 (dh adds 1<<14)
    //  2w stride: 2*64       = w<<7  (dw adds 64)
    const int o = (b << 22) + (h << 15) + (w << 7) + c4;

    out[o]                  = v;   // (2h,   2w)
    out[o + 64]             = v;   // (2h,   2w+1)
    out[o + (1 << 14)]      = v;   // (2h+1, 2w)
    out[o + (1 << 14) + 64] = v;   // (2h+1, 2w+1)
}

extern "C" void kernel_launch(void* const* d_in, const int* in_sizes, int n_in,
                              void* d_out, int out_size)
{
    const float4* in  = (const float4*)d_in[0];
    float4*       out = (float4*)d_out;

    const int n4 = 8 * 128 * 128 * 64;   // 8,388,608 float4 elements
    const int threads = 512;
    const int blocks  = n4 / threads;    // 16384

    upsample2x_kernel<<<blocks, threads>>>(in, out);
}